// round 1
// baseline (speedup 1.0000x reference)
#include <cuda_runtime.h>
#include <cuda_bf16.h>
#include <mma.h>
#include <math.h>

using namespace nvcuda;

#define D_DIM 128
#define V_DIM 100000
#define N_DIM 20000
#define E_DIM 640000
#define NODES_PER_BLK 64
#define NBLK ((N_DIM + NODES_PER_BLK - 1) / NODES_PER_BLK)   // 313

// ---------------- scratch (device globals; no runtime allocation) ----------
__device__ int   g_rowptr[N_DIM + 1];
__device__ float g_xagg[(size_t)N_DIM * D_DIM];              // 10.24 MB
__device__ __nv_bfloat16 g_wm[D_DIM * 2 * D_DIM];            // [128][256] bf16
__device__ float g_partials[NBLK * D_DIM];

// ---------------- K1: rowptr from sorted segment_ids ----------------------
__global__ void rowptr_kernel(const int* __restrict__ seg) {
    int e = blockIdx.x * blockDim.x + threadIdx.x;
    if (e >= E_DIM) return;
    int s = seg[e];
    if (e == 0) {
        for (int t = 0; t <= s; ++t) g_rowptr[t] = 0;
    } else {
        int p = seg[e - 1];
        for (int t = p + 1; t <= s; ++t) g_rowptr[t] = e;
    }
    if (e == E_DIM - 1) {
        for (int t = s + 1; t <= N_DIM; ++t) g_rowptr[t] = E_DIM;
    }
}

// ---------------- K2: pack [W | M] as bf16 [128][256] ---------------------
__global__ void packwm_kernel(const float* __restrict__ W,
                              const float* __restrict__ M) {
    int i = blockIdx.x * blockDim.x + threadIdx.x;   // 0 .. 32767
    if (i >= D_DIM * 2 * D_DIM) return;
    int d = i >> 8;          // row (output channel)
    int k = i & 255;         // combined K
    float v = (k < D_DIM) ? W[d * D_DIM + k] : M[d * D_DIM + (k - D_DIM)];
    g_wm[i] = __float2bfloat16(v);
}

// ---------------- K3: gather + segment-sum (one block per node) -----------
// 128 threads: lane = float4 column (32 x 16B = 512B row), warp id = edge slot.
__global__ void agg_kernel(const int* __restrict__ nbr,
                           const float* __restrict__ emb) {
    int n = blockIdx.x;
    int start = g_rowptr[n];
    int end   = g_rowptr[n + 1];
    int lane = threadIdx.x & 31;
    int w    = threadIdx.x >> 5;

    float4 acc = make_float4(0.f, 0.f, 0.f, 0.f);
    for (int e = start + w; e < end; e += 4) {
        int r = __ldg(&nbr[e]);
        float4 v = __ldg(((const float4*)(emb + (size_t)r * D_DIM)) + lane);
        acc.x += v.x; acc.y += v.y; acc.z += v.z; acc.w += v.w;
    }
    __shared__ float4 sbuf[4][32];
    sbuf[w][lane] = acc;
    __syncthreads();
    if (w == 0) {
        float4 a = sbuf[0][lane], b = sbuf[1][lane];
        float4 c = sbuf[2][lane], d = sbuf[3][lane];
        float4 o = make_float4(a.x + b.x + c.x + d.x,
                               a.y + b.y + c.y + d.y,
                               a.z + b.z + c.z + d.z,
                               a.w + b.w + c.w + d.w);
        ((float4*)(g_xagg + (size_t)n * D_DIM))[lane] = o;
    }
}

// ---------------- K4: relu(X @ [W|M]^T) + row-reduce via wmma bf16 --------
// Block: 64 nodes x 128 outputs, K=256. 256 threads = 8 warps (4 row x 2 col).
// Dyn smem: [0,64K) WM bf16 [128][256]; [64K,96K) A bf16 [64][256] -> later C f32 [64][128]
__global__ void gemm_kernel(const int* __restrict__ node_ids,
                            const float* __restrict__ emb) {
    extern __shared__ unsigned char dynsmem[];
    __nv_bfloat16* WMs = (__nv_bfloat16*)dynsmem;
    __nv_bfloat16* As  = (__nv_bfloat16*)(dynsmem + 65536);
    float*         Cs  = (float*)(dynsmem + 65536);

    const int tid = threadIdx.x;
    const int n0 = blockIdx.x * NODES_PER_BLK;

    // copy packed WM (64KB) as 16B chunks
    {
        const uint4* src = (const uint4*)g_wm;
        uint4* dst = (uint4*)WMs;
        #pragma unroll
        for (int i = tid; i < 4096; i += 256) dst[i] = src[i];
    }
    // build A: rows = nodes, cols 0..127 = emb[node], 128..255 = xagg[node]
    for (int idx = tid; idx < NODES_PER_BLK * 64; idx += 256) {
        int r = idx >> 6;
        int c = (idx & 63) << 2;
        int n = n0 + r;
        float4 v = make_float4(0.f, 0.f, 0.f, 0.f);
        if (n < N_DIM) {
            if (c < D_DIM) {
                int nid = __ldg(&node_ids[n]);
                v = *(const float4*)(emb + (size_t)nid * D_DIM + c);
            } else {
                v = *(const float4*)(g_xagg + (size_t)n * D_DIM + (c - D_DIM));
            }
        }
        __nv_bfloat162* dst = (__nv_bfloat162*)(As + r * 256 + c);
        dst[0] = __float22bfloat162_rn(make_float2(v.x, v.y));
        dst[1] = __float22bfloat162_rn(make_float2(v.z, v.w));
    }
    __syncthreads();

    const int w  = tid >> 5;
    const int wr = w >> 1;        // 0..3  (16-row band)
    const int wc = w & 1;         // 0..1  (64-col band)

    wmma::fragment<wmma::accumulator, 16, 16, 16, float> cf[4];
    #pragma unroll
    for (int j = 0; j < 4; ++j) wmma::fill_fragment(cf[j], 0.0f);

    #pragma unroll
    for (int kk = 0; kk < 16; ++kk) {
        wmma::fragment<wmma::matrix_a, 16, 16, 16, __nv_bfloat16, wmma::row_major> af;
        wmma::load_matrix_sync(af, As + (wr * 16) * 256 + kk * 16, 256);
        #pragma unroll
        for (int j = 0; j < 4; ++j) {
            wmma::fragment<wmma::matrix_b, 16, 16, 16, __nv_bfloat16, wmma::col_major> bf;
            wmma::load_matrix_sync(bf, WMs + (wc * 64 + j * 16) * 256 + kk * 16, 256);
            wmma::mma_sync(cf[j], af, bf, cf[j]);
        }
    }
    __syncthreads();   // everyone done reading A before we overwrite with C

    #pragma unroll
    for (int j = 0; j < 4; ++j) {
        #pragma unroll
        for (int t = 0; t < cf[j].num_elements; ++t)
            cf[j].x[t] = fmaxf(cf[j].x[t], 0.0f);
        wmma::store_matrix_sync(Cs + (wr * 16) * D_DIM + wc * 64 + j * 16,
                                cf[j], D_DIM, wmma::mem_row_major);
    }
    __syncthreads();

    // column-sum the 64x128 relu'd tile -> partials[block][128]
    __shared__ float red[256];
    {
        int col  = tid & 127;
        int part = tid >> 7;            // 0/1 -> rows [0,32) / [32,64)
        float s = 0.f;
        #pragma unroll
        for (int r = part * 32; r < part * 32 + 32; ++r)
            s += Cs[r * D_DIM + col];
        red[tid] = s;
    }
    __syncthreads();
    if (tid < 128)
        g_partials[blockIdx.x * D_DIM + tid] = red[tid] + red[tid + 128];
}

// ---------------- K5: reduce partials + softmax ----------------------------
__global__ void final_kernel(float* __restrict__ out) {
    const int tid = threadIdx.x;          // 512 threads
    const int col = tid & 127;
    const int q   = tid >> 7;             // quarter
    float acc = 0.f;
    for (int b = q; b < NBLK; b += 4)
        acc += g_partials[b * D_DIM + col];

    __shared__ float buf[512];
    buf[tid] = acc;
    __syncthreads();
    float logit = 0.f;
    if (tid < 128)
        logit = buf[tid] + buf[tid + 128] + buf[tid + 256] + buf[tid + 384];
    __syncthreads();

    buf[tid] = (tid < 128) ? logit : -INFINITY;
    __syncthreads();
    for (int st = 256; st > 0; st >>= 1) {
        if (tid < st) buf[tid] = fmaxf(buf[tid], buf[tid + st]);
        __syncthreads();
    }
    float mx = buf[0];
    __syncthreads();

    float e = (tid < 128) ? expf(logit - mx) : 0.f;
    buf[tid] = e;
    __syncthreads();
    for (int st = 256; st > 0; st >>= 1) {
        if (tid < st) buf[tid] += buf[tid + st];
        __syncthreads();
    }
    if (tid < 128) out[tid] = e / buf[0];
}

// ---------------- launcher --------------------------------------------------
extern "C" void kernel_launch(void* const* d_in, const int* in_sizes, int n_in,
                              void* d_out, int out_size) {
    const int*   node_ids     = (const int*)d_in[0];
    const int*   neighbor_ids = (const int*)d_in[1];
    const int*   segment_ids  = (const int*)d_in[2];
    const float* W            = (const float*)d_in[3];
    const float* M            = (const float*)d_in[4];
    const float* emb          = (const float*)d_in[5];
    float*       out          = (float*)d_out;

    cudaFuncSetAttribute(gemm_kernel,
                         cudaFuncAttributeMaxDynamicSharedMemorySize, 98304);

    rowptr_kernel<<<(E_DIM + 255) / 256, 256>>>(segment_ids);
    packwm_kernel<<<(D_DIM * 2 * D_DIM + 255) / 256, 256>>>(W, M);
    agg_kernel<<<N_DIM, 128>>>(neighbor_ids, emb);
    gemm_kernel<<<NBLK, 256, 98304>>>(node_ids, emb);
    final_kernel<<<1, 512>>>(out);
}

// round 2
// speedup vs baseline: 1.4187x; 1.4187x over previous
#include <cuda_runtime.h>
#include <cuda_bf16.h>
#include <mma.h>
#include <math.h>

using namespace nvcuda;

#define D_DIM 128
#define V_DIM 100000
#define N_DIM 20000
#define E_DIM 640000
#define NODES_PER_BLK 64
#define NBLK ((N_DIM + NODES_PER_BLK - 1) / NODES_PER_BLK)   // 313

// padded strides (conflict-free LDSM: row shift = 4 banks)
#define SA 264                 // bf16 elems per row for A / WM stage (528 B)
#define SC 132                 // float elems per row for C        (528 B)
#define WM_STAGE_BYTES (128 * SA * 2)                 // 67584
#define A_BYTES        (64  * SA * 2)                 // 33792
#define DYN_SMEM_BYTES (WM_STAGE_BYTES + A_BYTES)     // 101376

// ---------------- scratch (device globals; no runtime allocation) ----------
__device__ int   g_rowptr[N_DIM + 1];
__device__ float g_xagg[(size_t)N_DIM * D_DIM];              // 10.24 MB
__device__ __nv_bfloat16 g_wm[D_DIM * 2 * D_DIM];            // [128][256] bf16
__device__ float g_partials[NBLK * D_DIM];

// ---------------- K1: rowptr from sorted segment_ids ----------------------
__global__ void rowptr_kernel(const int* __restrict__ seg) {
    int e = blockIdx.x * blockDim.x + threadIdx.x;
    if (e >= E_DIM) return;
    int s = seg[e];
    if (e == 0) {
        for (int t = 0; t <= s; ++t) g_rowptr[t] = 0;
    } else {
        int p = seg[e - 1];
        for (int t = p + 1; t <= s; ++t) g_rowptr[t] = e;
    }
    if (e == E_DIM - 1) {
        for (int t = s + 1; t <= N_DIM; ++t) g_rowptr[t] = E_DIM;
    }
}

// ---------------- K2: pack [W | M] as bf16 [128][256] ---------------------
__global__ void packwm_kernel(const float* __restrict__ W,
                              const float* __restrict__ M) {
    int i = blockIdx.x * blockDim.x + threadIdx.x;   // 0 .. 32767
    if (i >= D_DIM * 2 * D_DIM) return;
    int d = i >> 8;          // row (output channel)
    int k = i & 255;         // combined K
    float v = (k < D_DIM) ? W[d * D_DIM + k] : M[d * D_DIM + (k - D_DIM)];
    g_wm[i] = __float2bfloat16(v);
}

// ---------------- K3: gather + segment-sum (one block per node) -----------
__global__ void agg_kernel(const int* __restrict__ nbr,
                           const float* __restrict__ emb) {
    int n = blockIdx.x;
    int start = g_rowptr[n];
    int end   = g_rowptr[n + 1];
    int lane = threadIdx.x & 31;
    int w    = threadIdx.x >> 5;

    float4 acc = make_float4(0.f, 0.f, 0.f, 0.f);
    for (int e = start + w; e < end; e += 4) {
        int r = __ldg(&nbr[e]);
        float4 v = __ldg(((const float4*)(emb + (size_t)r * D_DIM)) + lane);
        acc.x += v.x; acc.y += v.y; acc.z += v.z; acc.w += v.w;
    }
    __shared__ float4 sbuf[4][32];
    sbuf[w][lane] = acc;
    __syncthreads();
    if (w == 0) {
        float4 a = sbuf[0][lane], b = sbuf[1][lane];
        float4 c = sbuf[2][lane], d = sbuf[3][lane];
        float4 o = make_float4(a.x + b.x + c.x + d.x,
                               a.y + b.y + c.y + d.y,
                               a.z + b.z + c.z + d.z,
                               a.w + b.w + c.w + d.w);
        ((float4*)(g_xagg + (size_t)n * D_DIM))[lane] = o;
    }
}

// ---------------- K4: relu(X @ [W|M]^T) + row-reduce via wmma bf16 --------
// Block: 64 nodes x 128 outputs, K=256. 256 threads = 8 warps.
// Warp w owns output cols [16w, 16w+16). kk-outer loop: each B fragment
// loaded ONCE per warp; cf[4] accumulators (one per 16-row band).
// Dyn smem: [0, 67584)       WM stage, bf16 [128][264] padded (resident)
//           [67584, 101376)  A bf16 [64][264]  -> overlaid by C f32 [64][132]
__global__ __launch_bounds__(256)
void gemm_kernel(const int* __restrict__ node_ids,
                 const float* __restrict__ emb) {
    extern __shared__ unsigned char dynsmem[];
    __nv_bfloat16* WMs = (__nv_bfloat16*)dynsmem;                    // [128][SA]
    __nv_bfloat16* As  = (__nv_bfloat16*)(dynsmem + WM_STAGE_BYTES); // [64][SA]
    float*         Cs  = (float*)(dynsmem + WM_STAGE_BYTES);         // [64][SC]

    const int tid = threadIdx.x;
    const int w   = tid >> 5;
    const int n0  = blockIdx.x * NODES_PER_BLK;

    // stage WM into padded smem rows (row = 32 real uint4, stride 33 uint4)
    {
        const uint4* src = (const uint4*)g_wm;
        uint4* dst = (uint4*)WMs;
        #pragma unroll
        for (int i = tid; i < 4096; i += 256) {
            int r = i >> 5, c = i & 31;
            dst[r * 33 + c] = src[i];
        }
    }
    // build A: rows = nodes, cols 0..127 = emb[node], 128..255 = xagg[node]
    for (int idx = tid; idx < NODES_PER_BLK * 64; idx += 256) {
        int r = idx >> 6;
        int c = (idx & 63) << 2;
        int n = n0 + r;
        float4 v = make_float4(0.f, 0.f, 0.f, 0.f);
        if (n < N_DIM) {
            if (c < D_DIM) {
                int nid = __ldg(&node_ids[n]);
                v = *(const float4*)(emb + (size_t)nid * D_DIM + c);
            } else {
                v = *(const float4*)(g_xagg + (size_t)n * D_DIM + (c - D_DIM));
            }
        }
        __nv_bfloat162* dst = (__nv_bfloat162*)(As + r * SA + c);
        dst[0] = __float22bfloat162_rn(make_float2(v.x, v.y));
        dst[1] = __float22bfloat162_rn(make_float2(v.z, v.w));
    }
    __syncthreads();

    // compute: kk-outer, B fragment loaded once per kk
    wmma::fragment<wmma::accumulator, 16, 16, 16, float> cf[4];
    #pragma unroll
    for (int b = 0; b < 4; ++b) wmma::fill_fragment(cf[b], 0.0f);

    #pragma unroll
    for (int kk = 0; kk < 16; ++kk) {
        wmma::fragment<wmma::matrix_b, 16, 16, 16, __nv_bfloat16, wmma::col_major> bf;
        wmma::load_matrix_sync(bf, WMs + (w * 16) * SA + kk * 16, SA);
        #pragma unroll
        for (int b = 0; b < 4; ++b) {
            wmma::fragment<wmma::matrix_a, 16, 16, 16, __nv_bfloat16, wmma::row_major> af;
            wmma::load_matrix_sync(af, As + (b * 16) * SA + kk * 16, SA);
            wmma::mma_sync(cf[b], af, bf, cf[b]);
        }
    }
    __syncthreads();   // all warps done reading A before overlay with C

    #pragma unroll
    for (int b = 0; b < 4; ++b) {
        #pragma unroll
        for (int t = 0; t < cf[b].num_elements; ++t)
            cf[b].x[t] = fmaxf(cf[b].x[t], 0.0f);
        wmma::store_matrix_sync(Cs + (b * 16) * SC + w * 16, cf[b], SC,
                                wmma::mem_row_major);
    }
    __syncthreads();

    // column-sum the 64x128 relu'd tile (padded stride SC) -> partials
    __shared__ float red[256];
    {
        int col  = tid & 127;
        int part = tid >> 7;            // 0/1 -> rows [0,32) / [32,64)
        float s = 0.f;
        #pragma unroll
        for (int r = part * 32; r < part * 32 + 32; ++r)
            s += Cs[r * SC + col];
        red[tid] = s;
    }
    __syncthreads();
    if (tid < 128)
        g_partials[blockIdx.x * D_DIM + tid] = red[tid] + red[tid + 128];
}

// ---------------- K5: reduce partials + softmax ----------------------------
__global__ void final_kernel(float* __restrict__ out) {
    const int tid = threadIdx.x;          // 512 threads
    const int col = tid & 127;
    const int q   = tid >> 7;             // quarter
    float acc = 0.f;
    for (int b = q; b < NBLK; b += 4)
        acc += g_partials[b * D_DIM + col];

    __shared__ float buf[512];
    buf[tid] = acc;
    __syncthreads();
    float logit = 0.f;
    if (tid < 128)
        logit = buf[tid] + buf[tid + 128] + buf[tid + 256] + buf[tid + 384];
    __syncthreads();

    buf[tid] = (tid < 128) ? logit : -INFINITY;
    __syncthreads();
    for (int st = 256; st > 0; st >>= 1) {
        if (tid < st) buf[tid] = fmaxf(buf[tid], buf[tid + st]);
        __syncthreads();
    }
    float mx = buf[0];
    __syncthreads();

    float e = (tid < 128) ? expf(logit - mx) : 0.f;
    buf[tid] = e;
    __syncthreads();
    for (int st = 256; st > 0; st >>= 1) {
        if (tid < st) buf[tid] += buf[tid + st];
        __syncthreads();
    }
    if (tid < 128) out[tid] = e / buf[0];
}

// ---------------- launcher --------------------------------------------------
extern "C" void kernel_launch(void* const* d_in, const int* in_sizes, int n_in,
                              void* d_out, int out_size) {
    const int*   node_ids     = (const int*)d_in[0];
    const int*   neighbor_ids = (const int*)d_in[1];
    const int*   segment_ids  = (const int*)d_in[2];
    const float* W            = (const float*)d_in[3];
    const float* M            = (const float*)d_in[4];
    const float* emb          = (const float*)d_in[5];
    float*       out          = (float*)d_out;

    cudaFuncSetAttribute(gemm_kernel,
                         cudaFuncAttributeMaxDynamicSharedMemorySize,
                         DYN_SMEM_BYTES);

    rowptr_kernel<<<(E_DIM + 255) / 256, 256>>>(segment_ids);
    packwm_kernel<<<(D_DIM * 2 * D_DIM + 255) / 256, 256>>>(W, M);
    agg_kernel<<<N_DIM, 128>>>(neighbor_ids, emb);
    gemm_kernel<<<NBLK, 256, DYN_SMEM_BYTES>>>(node_ids, emb);
    final_kernel<<<1, 512>>>(out);
}